// round 2
// baseline (speedup 1.0000x reference)
#include <cuda_runtime.h>
#include <math.h>

#define KTOK 2048
#define DDIM 2048
#define NBATCH 16
#define MAXIT 50
#define EPSF 1e-8f
#define STEPSZ (0.1f / 2048.0f)

#define NBLK 128
#define NTHR 256
#define NWARP 8
#define ROWS 16                 // tokens per CTA
#define RPW 2                   // rows per warp
#define DPT (DDIM / NTHR)       // 8 d-elements per thread
#define DSL (DDIM / NBLK)       // 16 d-elements per CTA slice

#define SMEM_FLOATS (ROWS * DDIM + DDIM + 32 + 64)
#define SMEM_BYTES (SMEM_FLOATS * 4)

// ---------------- global scratch (no allocations allowed) ----------------
__device__ float g_m[DDIM];
__device__ float g_grad[2][DDIM];
__device__ float g_slam[2];
__device__ float g_viol;
__device__ volatile unsigned g_flags[NBLK];
__device__ volatile unsigned g_gen;

// ---------------- grid barrier: flag array + single gen broadcast --------
__device__ __forceinline__ void grid_bar(unsigned phase)
{
    __syncthreads();
    __threadfence();                       // release (gpu scope -> L1 inval too)
    if (blockIdx.x == 0) {
        if (threadIdx.x == 0) g_flags[0] = phase;
        if (threadIdx.x < NBLK) {
            while (g_flags[threadIdx.x] < phase) __nanosleep(64);
        }
        __syncthreads();
        if (threadIdx.x == 0) { __threadfence(); g_gen = phase; }
    } else {
        if (threadIdx.x == 0) {
            g_flags[blockIdx.x] = phase;
            while (g_gen < phase) __nanosleep(64);
        }
    }
    __syncthreads();
    __threadfence();                       // acquire + L1D invalidate
}

// deterministic block-wide sum: identical value on every thread & every CTA
__device__ __forceinline__ float block_sum(float v, float *red)
{
#pragma unroll
    for (int o = 16; o > 0; o >>= 1) v += __shfl_down_sync(0xffffffffu, v, o);
    __syncthreads();
    if ((threadIdx.x & 31) == 0) red[threadIdx.x >> 5] = v;
    __syncthreads();
    float s = red[0];
#pragma unroll
    for (int i = 1; i < NWARP; i++) s += red[i];
    __syncthreads();
    return s;
}

// log_map_at coefficients: v_k = -lam*p + mu*x_k, scalars only.
__device__ __forceinline__ void lam_mu(float dot, float xs, float p_sq,
                                       float &lam, float &mu)
{
    const float xy  = -dot;                        // (-p) . x_k
    const float xsc = fminf(p_sq, 0.99f);
    const float ysc = fminf(xs, 0.99f);
    const float a   = 1.0f + 2.0f * xy + ysc;      // coeff on (-p)
    const float b   = 1.0f - xsc;                  // coeff on x_k
    const float den = fmaxf(1.0f + 2.0f * xy + xsc * ysc, EPSF);
    const float numsq = fmaxf(a * a * p_sq + b * b * xs - 2.0f * a * b * dot, 0.0f);
    const float rn  = sqrtf(numsq) / den;
    const float maxn = 1.0f - EPSF;
    const float c   = (rn >= maxn) ? (maxn - EPSF) / rn : 1.0f;
    const float n   = rn * c;
    const float s   = fminf(n, 1.0f - EPSF);
    const float scale = 2.0f * atanhf(s) / (n + EPSF);
    const float t   = (n < EPSF) ? 0.0f : scale * c / den;
    lam = t * a;
    mu  = t * b;
}

__global__ void __launch_bounds__(NTHR, 1)
traj_kernel(const float *__restrict__ in, float *__restrict__ out)
{
    extern __shared__ float smem[];
    float *Xs  = smem;                 // [ROWS][DDIM]
    float *Ps  = Xs + ROWS * DDIM;     // [DDIM] center, redundant per CTA
    float *red = Ps + DDIM;            // [32]
    float *aux = red + 32;             // [64]: [0..15]=xsq, [16..31]=w0, [32..47]=mu

    const int tid  = threadIdx.x;
    const int blk  = blockIdx.x;
    const int lane = tid & 31;
    const int w    = tid >> 5;
    const int ds   = blk * DSL;

    const unsigned base = g_gen;       // launch-relative phase baseline
    unsigned cnt = 0;

    // ---- zero global scratch slices ----
    if (tid < DSL) {
        g_m[ds + tid] = 0.0f;
        g_grad[0][ds + tid] = 0.0f;
        g_grad[1][ds + tid] = 0.0f;
    }
    if (blk == 0 && tid == 0) { g_viol = 0.0f; g_slam[0] = 0.0f; g_slam[1] = 0.0f; }

    // ---- load tokens: X[k,:] = mean_b in[k,b,:]; xsq per row ----
    const float inv_b = 1.0f / (float)NBATCH;
    for (int rr = 0; rr < RPW; rr++) {
        const int r = w * RPW + rr;
        const int k = blk * ROWS + r;
        const float4 *src = (const float4 *)(in + (size_t)k * NBATCH * DDIM);
        float4 *dst = (float4 *)(Xs + r * DDIM);
        float ss = 0.0f;
        for (int j = 0; j < DDIM / 128; j++) {
            const int d4 = lane + j * 32;
            float4 a = make_float4(0.f, 0.f, 0.f, 0.f);
#pragma unroll
            for (int b = 0; b < NBATCH; b++) {
                float4 t = src[b * (DDIM / 4) + d4];
                a.x += t.x; a.y += t.y; a.z += t.z; a.w += t.w;
            }
            a.x *= inv_b; a.y *= inv_b; a.z *= inv_b; a.w *= inv_b;
            dst[d4] = a;
            ss += a.x * a.x + a.y * a.y + a.z * a.z + a.w * a.w;
        }
#pragma unroll
        for (int o = 16; o > 0; o >>= 1) ss += __shfl_down_sync(0xffffffffu, ss, o);
        if (lane == 0) aux[r] = ss;
    }
    __syncthreads();

    // w0_k = log_map0 scale / K
    if (tid < ROWS) {
        const float xs = aux[tid];
        const float n  = sqrtf(xs);
        const float s  = fminf(n, 1.0f - EPSF);
        const float sc = (n < EPSF) ? 0.0f : atanhf(s) / (n + EPSF);
        aux[16 + tid] = sc * (1.0f / (float)KTOK);
    }
    __syncthreads();

    grid_bar(base + ++cnt);            // zeroing complete chip-wide

    // ---- m partial: this CTA adds sum_r w0_r * X[r,:] over ALL d ----
    for (int j = 0; j < DPT; j++) {
        const int d = tid + j * NTHR;
        float acc = 0.0f;
#pragma unroll
        for (int r = 0; r < ROWS; r++) acc += aux[16 + r] * Xs[r * DDIM + d];
        atomicAdd(&g_m[d], acc);
    }

    grid_bar(base + ++cnt);            // m complete

    // ---- p0 = exp_map0(m), redundant per CTA ----
    float p_sq;
    {
        float part = 0.0f, ml[DPT];
        for (int j = 0; j < DPT; j++) {
            ml[j] = __ldcg(&g_m[tid + j * NTHR]);
            part += ml[j] * ml[j];
        }
        const float msq = block_sum(part, red);
        const float n   = sqrtf(msq);
        const float sc  = (n < EPSF) ? 0.0f : tanhf(n) / (n + EPSF);
        for (int j = 0; j < DPT; j++) Ps[tid + j * NTHR] = sc * ml[j];
        p_sq = sc * sc * msq;
        __syncthreads();
    }

    // =================== Karcher loop ===================
    for (int it = 0; it < MAXIT; it++) {
        const int b = it & 1, nb = b ^ 1;

        // Phase 1: dots + lam/mu for own rows; accumulate S_lam and X^T mu
        float lamacc = 0.0f;
        for (int rr = 0; rr < RPW; rr++) {
            const int r = w * RPW + rr;
            const float *xr = Xs + r * DDIM;
            float p2 = 0.0f;
            for (int j = 0; j < DDIM / 32; j++) {
                const int d = lane + j * 32;
                p2 += xr[d] * Ps[d];
            }
#pragma unroll
            for (int o = 16; o > 0; o >>= 1) p2 += __shfl_down_sync(0xffffffffu, p2, o);
            if (lane == 0) {
                float lam, mu;
                lam_mu(p2, aux[r], p_sq, lam, mu);
                aux[32 + r] = mu;
                lamacc += lam;
            }
        }
        if (lane == 0) atomicAdd(&g_slam[b], lamacc);
        __syncthreads();                // mu values visible

        for (int j = 0; j < DPT; j++) {
            const int d = tid + j * NTHR;
            float acc = 0.0f;
#pragma unroll
            for (int r = 0; r < ROWS; r++) acc += aux[32 + r] * Xs[r * DDIM + d];
            atomicAdd(&g_grad[b][d], acc);
        }

        grid_bar(base + ++cnt);         // grad complete

        // Phase 2: redundant p update per CTA
        const float slam = __ldcg(&g_slam[b]);
        float gl[DPT], a1 = 0.0f, a2 = 0.0f;
        for (int j = 0; j < DPT; j++) {
            const int d = tid + j * NTHR;
            const float g = __ldcg(&g_grad[b][d]) - Ps[d] * slam;
            gl[j] = g;
            a1 += g * g;
            a2 += Ps[d] * g;
        }
        const float gg = block_sum(a1, red);
        const float pg = block_sum(a2, red);

        // zero next-iteration buffers (safe: nb last read before previous bar)
        if (tid < DSL) g_grad[nb][ds + tid] = 0.0f;
        if (blk == 0 && tid == 0) g_slam[nb] = 0.0f;

        const float n_v = STEPSZ * sqrtf(gg);
        if (n_v >= EPSF) {
            const float sc  = tanhf(0.5f * n_v) / (n_v + EPSF);
            const float xy  = -STEPSZ * sc * pg;
            const float ysq = STEPSZ * STEPSZ * sc * sc * gg;
            const float xsc = fminf(p_sq, 0.99f);
            const float ysc = fminf(ysq, 0.99f);
            const float A   = 1.0f + 2.0f * xy + ysc;
            const float B   = 1.0f - xsc;
            const float dn  = fmaxf(1.0f + 2.0f * xy + xsc * ysc, EPSF);
            const float ca  = A / dn;
            const float cb  = (-STEPSZ * sc) * B / dn;
            float pp = 0.0f;
            for (int j = 0; j < DPT; j++) {
                const int d = tid + j * NTHR;
                const float nv = ca * Ps[d] + cb * gl[j];
                Ps[d] = nv;
                pp += nv * nv;
            }
            float rsq = block_sum(pp, red);
            const float rn = sqrtf(rsq);
            if (rn >= 1.0f - EPSF) {
                const float cf = (1.0f - 2.0f * EPSF) / rn;
                for (int j = 0; j < DPT; j++) Ps[tid + j * NTHR] *= cf;
                rsq *= cf * cf;
            }
            p_sq = rsq;
        }
        __syncthreads();

        grid_bar(base + ++cnt);         // zeroing + update settled
    }

    // ---- final distances + violation ----
    float vi = 0.0f;
    for (int rr = 0; rr < RPW; rr++) {
        const int r = w * RPW + rr;
        const float *xr = Xs + r * DDIM;
        float p2 = 0.0f;
        for (int j = 0; j < DDIM / 32; j++) {
            const int d = lane + j * 32;
            p2 += xr[d] * Ps[d];
        }
#pragma unroll
        for (int o = 16; o > 0; o >>= 1) p2 += __shfl_down_sync(0xffffffffu, p2, o);
        if (lane == 0) {
            const float xs  = aux[r];
            const float dsq = xs - 2.0f * p2 + p_sq;
            const float den = fmaxf((1.0f - xs) * (1.0f - p_sq), EPSF);
            const float fr  = fmaxf(dsq / den, 0.0f);
            const float dd  = asinhf(sqrtf(fr));
            vi += fmaxf(dd - 2.0f, 0.0f);
        }
    }
    if (lane == 0) atomicAdd(&g_viol, vi);

    grid_bar(base + ++cnt);

    if (blk == 0 && tid == 0) out[0] = g_viol * (1.0f / (float)KTOK);
}

extern "C" void kernel_launch(void* const* d_in, const int* in_sizes, int n_in,
                              void* d_out, int out_size)
{
    (void)in_sizes; (void)n_in; (void)out_size;
    cudaFuncSetAttribute(traj_kernel,
                         cudaFuncAttributeMaxDynamicSharedMemorySize, SMEM_BYTES);
    const float *in = (const float *)d_in[0];
    float *out = (float *)d_out;
    traj_kernel<<<NBLK, NTHR, SMEM_BYTES>>>(in, out);
}